// round 10
// baseline (speedup 1.0000x reference)
#include <cuda_runtime.h>
#include <stdint.h>

#define NP     65536
#define NA     1024
#define NMAX   512
#define GRID   100
#define CELLS  (GRID * GRID)
#define CAP    48          // max pts/cell; lambda=6.55 => P(>48) < 1e-20
#define TPB    256         // threads per block
#define PPB    (NP / NA)   // 64 points binned per block

// Scratch (allocation-free rule: __device__ globals)
__device__ int      g_cnt[CELLS];        // zero at entry; re-zeroed by each run
__device__ float4   g_bin[CELLS * CAP];  // packed (x,y,z,(float)pointIdx); idx<=65535 exact in f32
__device__ unsigned g_barrier;           // monotonic arrive counter (never reset)

static __device__ __forceinline__ int cell_of(float x, float y) {
    int gx = (int)floorf(x);          // cell size = 1.0
    int gy = (int)floorf(y);
    gx = min(GRID - 1, max(0, gx));
    gy = min(GRID - 1, max(0, gy));
    return gy * GRID + gx;
}

// All-resident software grid barrier. Safe because grid is single-wave
// (1024 blocks, launch_bounds(256,7) => 1036 concurrent on 148 SMs).
// Monotonic counter: exit target = next multiple of NA above my ticket,
// so it works across unlimited graph replays without ever resetting.
static __device__ __forceinline__ void grid_barrier(int tid) {
    __syncthreads();
    if (tid == 0) {
        __threadfence();                       // release my block's writes
        unsigned old = atomicAdd(&g_barrier, 1u);
        unsigned target = (old / (unsigned)NA + 1u) * (unsigned)NA;
        unsigned cur;
        do {
            asm volatile("ld.volatile.global.u32 %0, [%1];"
                         : "=r"(cur) : "l"(&g_barrier));
        } while (cur < target);
        __threadfence();                       // acquire others' writes
    }
    __syncthreads();
}

// ONE kernel: bin 64 pts/block -> grid barrier -> per-anchor grouping.
// g_cnt self-cleans (zeroed after barrier 2) for the next replay.
__global__ void __launch_bounds__(TPB, 7) k_fused(
    const float* __restrict__ pts,
    const float* __restrict__ anch,
    float* __restrict__ out,
    float* __restrict__ counts_out)
{
    int a = blockIdx.x;
    int tid = threadIdx.x;
    int lane = tid & 31;

    // ---- Phase 1: bin this block's 64 points (g_cnt is all-zero at entry) ----
    if (tid < PPB) {
        int p = a * PPB + tid;
        float x = __ldg(&pts[p * 3 + 0]);
        float y = __ldg(&pts[p * 3 + 1]);
        float z = __ldg(&pts[p * 3 + 2]);
        int c = cell_of(x, y);
        int pos = atomicAdd(&g_cnt[c], 1);
        if (pos < CAP) g_bin[c * CAP + pos] = make_float4(x, y, z, (float)p);
    }

    // ---- Anchor box setup (independent of phase 1; overlaps bin latency) ----
    const float2* arow = (const float2*)(anch + a * 6);
    float2 f01 = __ldg(&arow[0]);   // cx, cy
    float2 f23 = __ldg(&arow[1]);   // cz, w
    float2 f45 = __ldg(&arow[2]);   // l, h
    float cx = f01.x, cy = f01.y;
    float w = f23.y, l = f45.x, h = f45.y;
    float hw = w * 0.5f, hl = l * 0.5f;
    float x0 = cx - hw, x1 = cx + hw;
    float y0 = cy - hl, y1 = cy + hl;

    int gx0 = max(0, (int)floorf(x0));
    int gx1 = min(GRID - 1, (int)floorf(x1));
    int gy0 = max(0, (int)floorf(y0));
    int gy1 = min(GRID - 1, (int)floorf(y1));
    int ncx = gx1 - gx0 + 1;
    int ncy = gy1 - gy0 + 1;
    int ncells = ncx * ncy;   // <= 36 (w,l <= 5, cell = 1.0)

    __shared__ int           s_base[40];      // g_bin base per covered cell
    __shared__ int           s_ccnt[40];
    __shared__ int           s_off[40];       // exclusive offset per cell
    __shared__ int           s_total;
    __shared__ unsigned char s_cid[36 * CAP]; // candidate -> covered-cell id
    __shared__ float         s_key[NMAX];     // point index as float (exact)
    __shared__ float         s_px[NMAX], s_py[NMAX], s_pz[NMAX];
    __shared__ int           s_count;
    if (tid == 0) s_count = 0;

    // ---- Barrier 1: all binning complete, g_bin/g_cnt visible grid-wide ----
    grid_barrier(tid);

    // ---- Phase 2a: read covered cell counts ----
    if (tid < ncells) {
        int cgx = gx0 + (tid % ncx);
        int cgy = gy0 + (tid / ncx);
        int c = cgy * GRID + cgx;
        s_base[tid] = c * CAP;
        s_ccnt[tid] = min(g_cnt[c], CAP);
    }

    // ---- Barrier 2: all g_cnt reads done; safe to zero for next replay ----
    grid_barrier(tid);
    {
        int c0 = a * 10;                     // blocks 0..999 cover all 10000 cells
        if (c0 < CELLS && tid < 10) g_cnt[c0 + tid] = 0;
    }

    // ---- Phase 2b: offsets + candidate->cell table ----
    if (tid < ncells) {
        int off = 0;
        for (int j = 0; j < tid; j++) off += s_ccnt[j];
        s_off[tid] = off;
        int cnt = s_ccnt[tid];
        for (int k = 0; k < cnt; k++) s_cid[off + k] = (unsigned char)tid;
        if (tid == ncells - 1) s_total = off + cnt;
    }
    __syncthreads();

    int total = s_total;

    // ---- Phase A: test candidates; warp-aggregated compaction into shared ----
    for (int i0 = 0; i0 < total; i0 += TPB) {
        int i = i0 + tid;
        bool hit = false;
        float4 r = make_float4(0.f, 0.f, 0.f, 0.f);
        if (i < total) {
            int j = (int)s_cid[i];
            r = __ldg(&g_bin[s_base[j] + (i - s_off[j])]);
            hit = (r.x >= x0 && r.x <= x1 && r.y >= y0 && r.y <= y1 &&
                   r.z >= 0.0f && r.z <= h);
        }
        unsigned bal = __ballot_sync(0xFFFFFFFFu, hit);
        int nb = __popc(bal);
        int base = 0;
        if (lane == 0 && nb) base = atomicAdd(&s_count, nb);
        base = __shfl_sync(0xFFFFFFFFu, base, 0);
        if (hit) {
            int pos = base + __popc(bal & ((1u << lane) - 1u));
            if (pos < NMAX) {
                s_key[pos] = r.w;
                s_px[pos] = r.x; s_py[pos] = r.y; s_pz[pos] = r.z;
            }
        }
    }
    __syncthreads();

    int cnt = s_count;
    int m = min(cnt, NMAX);
    float* outa = out + (size_t)a * NMAX * 3;

    // ---- Zero tail [3m, 1536): scalar head to 16B boundary, then STG.128 ----
    int limit = 3 * m;
    int head_end = (limit + 3) & ~3;
    if (tid < head_end - limit) outa[limit + tid] = 0.0f;
    {
        float4 z4 = make_float4(0.f, 0.f, 0.f, 0.f);
        float4* outa4 = (float4*)outa;        // out is 16B-aligned (a*6144 bytes)
        for (int q = (head_end >> 2) + tid; q < NMAX * 3 / 4; q += TPB) outa4[q] = z4;
    }

    // ---- Rank-by-counting (broadcast LDS) + direct ranked store ----
    for (int s = tid; s < m; s += TPB) {
        float key = s_key[s];
        int r = 0;
        int j = 0;
        for (; j + 4 <= m; j += 4) {
            r += (s_key[j + 0] < key);
            r += (s_key[j + 1] < key);
            r += (s_key[j + 2] < key);
            r += (s_key[j + 3] < key);
        }
        for (; j < m; j++) r += (s_key[j] < key);
        outa[r * 3 + 0] = s_px[s] - cx;
        outa[r * 3 + 1] = s_py[s] - cy;
        outa[r * 3 + 2] = s_pz[s];
    }
    if (tid == 0) counts_out[a] = (float)cnt;
}

extern "C" void kernel_launch(void* const* d_in, const int* in_sizes, int n_in,
                              void* d_out, int out_size) {
    const float* pts  = (const float*)d_in[0];   // (65536, 3) f32
    const float* anch = (const float*)d_in[1];   // (1024, 6)  f32
    float* out = (float*)d_out;                  // 1024*512*3 f32, then 1024 counts
    float* counts_out = out + (size_t)NA * NMAX * 3;

    k_fused<<<NA, TPB>>>(pts, anch, out, counts_out);
}

// round 11
// speedup vs baseline: 1.0132x; 1.0132x over previous
#include <cuda_runtime.h>
#include <stdint.h>

#define NP     65536
#define NA     1024
#define NMAX   512
#define GRID   100
#define CELLS  (GRID * GRID)
#define CAP    48          // max pts/cell; lambda=6.55 => P(>48) < 1e-20
#define TPB    256         // threads per anchor block

// Scratch (allocation-free rule: __device__ globals). Zero-initialized at load.
__device__ int      g_cnt2[2 * CELLS];   // double-buffered cell counters
__device__ int      g_epoch;             // which buffer k_bin fills this call
__device__ unsigned g_done;              // monotonic k_bin block-completion counter
__device__ float4   g_bin[CELLS * CAP];  // packed (x,y,z,(float)pointIdx); idx<=65535 exact in f32

static __device__ __forceinline__ int cell_of(float x, float y) {
    int gx = (int)floorf(x);          // cell size = 1.0
    int gy = (int)floorf(y);
    gx = min(GRID - 1, max(0, gx));
    gy = min(GRID - 1, max(0, gy));
    return gy * GRID + gx;
}

// 1 point per thread. Bins into buf[e] (pre-zeroed by previous call), zeros
// buf[1-e] for the next call (nothing reads it this launch), last block flips
// the epoch. 256 blocks => trivially single-wave, so every block reads g_epoch
// before any block's done-increment can trigger the flip.
__global__ void k_bin(const float* __restrict__ pts) {
    int e = *((volatile int*)&g_epoch);
    int* cnt  = g_cnt2 + e * CELLS;
    int* cntn = g_cnt2 + (1 - e) * CELLS;

    int p = blockIdx.x * blockDim.x + threadIdx.x;
    if (p < CELLS) cntn[p] = 0;                     // zero next-call buffer

    float x = __ldg(&pts[p * 3 + 0]);
    float y = __ldg(&pts[p * 3 + 1]);
    float z = __ldg(&pts[p * 3 + 2]);
    int c = cell_of(x, y);
    int pos = atomicAdd(&cnt[c], 1);
    if (pos < CAP) g_bin[c * CAP + pos] = make_float4(x, y, z, (float)p);

    __syncthreads();
    if (threadIdx.x == 0) {
        __threadfence();
        unsigned old = atomicAdd(&g_done, 1u);
        if ((old % (unsigned)(NP / 256)) == (unsigned)(NP / 256) - 1u) {
            g_epoch = 1 - e;                        // visible at next launch boundary
            __threadfence();
        }
    }
}

// One block per anchor. 7 blocks/SM => 1036 concurrent, SINGLE WAVE.
// Coords cached in shared at test time => phase B has zero global loads.
__global__ void __launch_bounds__(TPB, 7) k_anchor(
    const float* __restrict__ anch,
    float* __restrict__ out,
    float* __restrict__ counts_out)
{
    int a = blockIdx.x;
    int tid = threadIdx.x;
    int lane = tid & 31;

    // k_bin flipped the epoch, so the filled buffer is buf[1 - g_epoch].
    const int* cnt = g_cnt2 + (1 - *((volatile int*)&g_epoch)) * CELLS;

    // Anchor row = 6 floats at byte offset a*24 (8-aligned): 3 broadcast LDG.64.
    const float2* arow = (const float2*)(anch + a * 6);
    float2 f01 = __ldg(&arow[0]);   // cx, cy
    float2 f23 = __ldg(&arow[1]);   // cz, w
    float2 f45 = __ldg(&arow[2]);   // l, h
    float cx = f01.x, cy = f01.y;
    float w = f23.y, l = f45.x, h = f45.y;
    float hw = w * 0.5f, hl = l * 0.5f;
    float x0 = cx - hw, x1 = cx + hw;
    float y0 = cy - hl, y1 = cy + hl;

    int gx0 = max(0, (int)floorf(x0));
    int gx1 = min(GRID - 1, (int)floorf(x1));
    int gy0 = max(0, (int)floorf(y0));
    int gy1 = min(GRID - 1, (int)floorf(y1));
    int ncx = gx1 - gx0 + 1;
    int ncy = gy1 - gy0 + 1;
    int ncells = ncx * ncy;   // <= 36 (w,l <= 5, cell = 1.0)

    __shared__ int           s_base[40];      // g_bin base per covered cell
    __shared__ int           s_ccnt[40];
    __shared__ int           s_off[40];       // exclusive offset per cell
    __shared__ int           s_total;
    __shared__ unsigned char s_cid[36 * CAP]; // candidate -> covered-cell id
    __shared__ float         s_key[NMAX];     // point index as float (exact)
    __shared__ float         s_px[NMAX], s_py[NMAX], s_pz[NMAX];
    __shared__ int           s_count;

    if (tid == 0) s_count = 0;
    if (tid < ncells) {
        int cgx = gx0 + (tid % ncx);
        int cgy = gy0 + (tid / ncx);
        int c = cgy * GRID + cgx;
        s_base[tid] = c * CAP;
        s_ccnt[tid] = min(cnt[c], CAP);
    }
    __syncthreads();                                   // (1)

    if (tid < ncells) {
        int off = 0;
        for (int j = 0; j < tid; j++) off += s_ccnt[j];
        s_off[tid] = off;
        int cc = s_ccnt[tid];
        for (int k = 0; k < cc; k++) s_cid[off + k] = (unsigned char)tid;
        if (tid == ncells - 1) s_total = off + cc;
    }
    __syncthreads();                                   // (2)

    int total = s_total;

    // Phase A: test candidates (usually one pass: total ~230 < 256), warp-
    // aggregated compaction of key AND coords into shared (order-free).
    for (int i0 = 0; i0 < total; i0 += TPB) {
        int i = i0 + tid;
        bool hit = false;
        float4 r = make_float4(0.f, 0.f, 0.f, 0.f);
        if (i < total) {
            int j = (int)s_cid[i];
            r = __ldg(&g_bin[s_base[j] + (i - s_off[j])]);
            hit = (r.x >= x0 && r.x <= x1 && r.y >= y0 && r.y <= y1 &&
                   r.z >= 0.0f && r.z <= h);
        }
        unsigned bal = __ballot_sync(0xFFFFFFFFu, hit);
        int nb = __popc(bal);
        int base = 0;
        if (lane == 0 && nb) base = atomicAdd(&s_count, nb);
        base = __shfl_sync(0xFFFFFFFFu, base, 0);
        if (hit) {
            int pos = base + __popc(bal & ((1u << lane) - 1u));
            if (pos < NMAX) {
                s_key[pos] = r.w;
                s_px[pos] = r.x; s_py[pos] = r.y; s_pz[pos] = r.z;
            }
        }
    }
    __syncthreads();                                   // (3)

    int cntv = s_count;
    int m = min(cntv, NMAX);
    float* outa = out + (size_t)a * NMAX * 3;

    // Zero the tail [3m, 1536): scalar head up to 16B boundary, then STG.128.
    int limit = 3 * m;
    int head_end = (limit + 3) & ~3;          // first float4-aligned index >= limit
    if (tid < head_end - limit) outa[limit + tid] = 0.0f;
    {
        float4 z4 = make_float4(0.f, 0.f, 0.f, 0.f);
        float4* outa4 = (float4*)outa;        // out is 16B-aligned (a*6144 bytes)
        for (int q = (head_end >> 2) + tid; q < NMAX * 3 / 4; q += TPB) outa4[q] = z4;
    }

    // Rank-by-counting (broadcast LDS) + direct ranked store. No global loads.
    for (int s = tid; s < m; s += TPB) {
        float key = s_key[s];
        int r = 0;
        int j = 0;
        for (; j + 4 <= m; j += 4) {
            r += (s_key[j + 0] < key);
            r += (s_key[j + 1] < key);
            r += (s_key[j + 2] < key);
            r += (s_key[j + 3] < key);
        }
        for (; j < m; j++) r += (s_key[j] < key);
        outa[r * 3 + 0] = s_px[s] - cx;
        outa[r * 3 + 1] = s_py[s] - cy;
        outa[r * 3 + 2] = s_pz[s];
    }
    if (tid == 0) counts_out[a] = (float)cntv;
}

extern "C" void kernel_launch(void* const* d_in, const int* in_sizes, int n_in,
                              void* d_out, int out_size) {
    const float* pts  = (const float*)d_in[0];   // (65536, 3) f32
    const float* anch = (const float*)d_in[1];   // (1024, 6)  f32
    float* out = (float*)d_out;                  // 1024*512*3 f32, then 1024 counts
    float* counts_out = out + (size_t)NA * NMAX * 3;

    k_bin<<<NP / 256, 256>>>(pts);
    k_anchor<<<NA, TPB>>>(anch, out, counts_out);
}

// round 13
// speedup vs baseline: 1.1356x; 1.1208x over previous
#include <cuda_runtime.h>
#include <stdint.h>

#define NP     65536
#define NA     1024
#define NMAX   512
#define GRID   100
#define CELLS  (GRID * GRID)
#define CAP    48          // max pts/cell; lambda=6.55 => P(>48) < 1e-20
#define TPB    256         // threads per anchor block
#define ZB     40          // blocks that clean g_cnt (40 * 250 = 10000 cells)

// Scratch (allocation-free rule: __device__ globals). Zero-initialized at load.
__device__ int      g_cnt[CELLS];        // all-zero at k_bin entry; self-cleaned by k_anchor
__device__ unsigned g_prolog;            // monotonic prologue-done counter (never reset)
__device__ float4   g_bin[CELLS * CAP];  // packed (x,y,z,(float)pointIdx); idx<=65535 exact in f32

static __device__ __forceinline__ int cell_of(float x, float y) {
    int gx = (int)floorf(x);          // cell size = 1.0
    int gy = (int)floorf(y);
    gx = min(GRID - 1, max(0, gx));
    gy = min(GRID - 1, max(0, gy));
    return gy * GRID + gx;
}

// 1 point per thread (65536 threads): bins the point AND zeroes its 96-byte
// share of the output (6.29MB / 65536 = 6 float4), fully coalesced.
__global__ void k_bin(const float* __restrict__ pts, float4* __restrict__ out4) {
    int p = blockIdx.x * blockDim.x + threadIdx.x;
    float x = __ldg(&pts[p * 3 + 0]);
    float y = __ldg(&pts[p * 3 + 1]);
    float z = __ldg(&pts[p * 3 + 2]);

    // Zero output: 393216 float4 total = 6 per thread, stride NP for coalescing.
    float4 z4 = make_float4(0.f, 0.f, 0.f, 0.f);
#pragma unroll
    for (int k = 0; k < 6; k++) out4[k * NP + p] = z4;

    int c = cell_of(x, y);
    int pos = atomicAdd(&g_cnt[c], 1);
    if (pos < CAP) g_bin[c * CAP + pos] = make_float4(x, y, z, (float)p);
}

// One block per anchor. 7 blocks/SM => 1036 concurrent, SINGLE WAVE.
// Output tail already zeroed by k_bin => epilogue is rank + 3m stores only.
// g_cnt self-cleans: blocks 0..39 zero it once ALL blocks' count-reads are done.
__global__ void __launch_bounds__(TPB, 7) k_anchor(
    const float* __restrict__ anch,
    float* __restrict__ out,
    float* __restrict__ counts_out)
{
    int a = blockIdx.x;
    int tid = threadIdx.x;
    int lane = tid & 31;

    // Anchor row = 6 floats at byte offset a*24 (8-aligned): 3 broadcast LDG.64.
    const float2* arow = (const float2*)(anch + a * 6);
    float2 f01 = __ldg(&arow[0]);   // cx, cy
    float2 f23 = __ldg(&arow[1]);   // cz, w
    float2 f45 = __ldg(&arow[2]);   // l, h
    float cx = f01.x, cy = f01.y;
    float w = f23.y, l = f45.x, h = f45.y;
    float hw = w * 0.5f, hl = l * 0.5f;
    float x0 = cx - hw, x1 = cx + hw;
    float y0 = cy - hl, y1 = cy + hl;

    int gx0 = max(0, (int)floorf(x0));
    int gx1 = min(GRID - 1, (int)floorf(x1));
    int gy0 = max(0, (int)floorf(y0));
    int gy1 = min(GRID - 1, (int)floorf(y1));
    int ncx = gx1 - gx0 + 1;
    int ncy = gy1 - gy0 + 1;
    int ncells = ncx * ncy;   // <= 36 (w,l <= 5, cell = 1.0)

    __shared__ int           s_base[40];      // g_bin base per covered cell
    __shared__ int           s_ccnt[40];
    __shared__ int           s_off[40];       // exclusive offset per cell
    __shared__ int           s_total;
    __shared__ unsigned char s_cid[36 * CAP]; // candidate -> covered-cell id
    __shared__ float         s_key[NMAX];     // point index as float (exact)
    __shared__ float         s_px[NMAX], s_py[NMAX], s_pz[NMAX];
    __shared__ int           s_count;

    if (tid == 0) s_count = 0;
    if (tid < ncells) {
        int cgx = gx0 + (tid % ncx);
        int cgy = gy0 + (tid / ncx);
        int c = cgy * GRID + cgx;
        s_base[tid] = c * CAP;
        s_ccnt[tid] = min(g_cnt[c], CAP);
    }
    __syncthreads();                                   // (1) count reads complete

    // Signal "this block is done reading g_cnt" (monotonic, replay-safe).
    unsigned my_ticket = 0;
    if (tid == 0) my_ticket = atomicAdd(&g_prolog, 1u);

    if (tid < ncells) {
        int off = 0;
        for (int j = 0; j < tid; j++) off += s_ccnt[j];
        s_off[tid] = off;
        int cc = s_ccnt[tid];
        for (int k = 0; k < cc; k++) s_cid[off + k] = (unsigned char)tid;
        if (tid == ncells - 1) s_total = off + cc;
    }
    __syncthreads();                                   // (2)

    int total = s_total;

    // Phase A: test candidates (usually one pass: total ~230 < 256), warp-
    // aggregated compaction of key AND coords into shared (order-free).
    for (int i0 = 0; i0 < total; i0 += TPB) {
        int i = i0 + tid;
        bool hit = false;
        float4 r = make_float4(0.f, 0.f, 0.f, 0.f);
        if (i < total) {
            int j = (int)s_cid[i];
            r = __ldg(&g_bin[s_base[j] + (i - s_off[j])]);
            hit = (r.x >= x0 && r.x <= x1 && r.y >= y0 && r.y <= y1 &&
                   r.z >= 0.0f && r.z <= h);
        }
        unsigned bal = __ballot_sync(0xFFFFFFFFu, hit);
        int nb = __popc(bal);
        int base = 0;
        if (lane == 0 && nb) base = atomicAdd(&s_count, nb);
        base = __shfl_sync(0xFFFFFFFFu, base, 0);
        if (hit) {
            int pos = base + __popc(bal & ((1u << lane) - 1u));
            if (pos < NMAX) {
                s_key[pos] = r.w;
                s_px[pos] = r.x; s_py[pos] = r.y; s_pz[pos] = r.z;
            }
        }
    }
    __syncthreads();                                   // (3)

    int cnt = s_count;
    int m = min(cnt, NMAX);
    float* outa = out + (size_t)a * NMAX * 3;

    // Rank-by-counting (broadcast LDS) + direct ranked store. Tail [3m,1536)
    // was zeroed by k_bin; we only write the 3m live floats.
    for (int s = tid; s < m; s += TPB) {
        float key = s_key[s];
        int r = 0;
        int j = 0;
        for (; j + 4 <= m; j += 4) {
            r += (s_key[j + 0] < key);
            r += (s_key[j + 1] < key);
            r += (s_key[j + 2] < key);
            r += (s_key[j + 3] < key);
        }
        for (; j < m; j++) r += (s_key[j] < key);
        outa[r * 3 + 0] = s_px[s] - cx;
        outa[r * 3 + 1] = s_py[s] - cy;
        outa[r * 3 + 2] = s_pz[s];
    }
    if (tid == 0) counts_out[a] = (float)cnt;

    // Deferred g_cnt cleaning: blocks 0..ZB-1 wait (fast-path: by the time any
    // epilogue runs, all prologues finished) until every block of THIS launch
    // has read its counts, then zero 250 cells each for the next launch.
    if (a < ZB) {
        if (tid == 0) {
            unsigned target = (my_ticket / (unsigned)NA + 1u) * (unsigned)NA;
            unsigned cur;
            do {
                asm volatile("ld.volatile.global.u32 %0, [%1];"
                             : "=r"(cur) : "l"(&g_prolog));
            } while (cur < target);
        }
        __syncthreads();
        if (tid < CELLS / ZB) g_cnt[a * (CELLS / ZB) + tid] = 0;
    }
}

extern "C" void kernel_launch(void* const* d_in, const int* in_sizes, int n_in,
                              void* d_out, int out_size) {
    const float* pts  = (const float*)d_in[0];   // (65536, 3) f32
    const float* anch = (const float*)d_in[1];   // (1024, 6)  f32
    float* out = (float*)d_out;                  // 1024*512*3 f32, then 1024 counts
    float* counts_out = out + (size_t)NA * NMAX * 3;

    k_bin<<<NP / 256, 256>>>(pts, (float4*)out);
    k_anchor<<<NA, TPB>>>(anch, out, counts_out);
}

// round 14
// speedup vs baseline: 1.1429x; 1.0064x over previous
#include <cuda_runtime.h>
#include <stdint.h>

#define NP     65536
#define NA     1024
#define NMAX   512
#define GRID   100
#define CELLS  (GRID * GRID)
#define CAP    48          // max pts/cell; lambda=6.55 => P(>48) < 1e-20
#define TPB    256         // threads per anchor block

// Scratch (allocation-free rule: __device__ globals). Zero-initialized at load.
__device__ int      g_cnt2[2 * CELLS];   // double-buffered counters; stale side is ALL ZERO
__device__ int      g_epoch;             // which buffer k_bin fills this launch
__device__ unsigned g_done;              // monotonic k_bin completion counter (never reset)
__device__ float4   g_bin[CELLS * CAP];  // packed (x,y,z,(float)pointIdx); idx<=65535 exact in f32

static __device__ __forceinline__ int cell_of(float x, float y) {
    int gx = (int)floorf(x);          // cell size = 1.0
    int gy = (int)floorf(y);
    gx = min(GRID - 1, max(0, gx));
    gy = min(GRID - 1, max(0, gy));
    return gy * GRID + gx;
}

// 1 point per thread (65536 threads, 256 blocks):
//  - zero the OTHER count buffer (for next launch; nothing reads it now)
//  - zero this thread's 96-byte share of the output (6 coalesced STG.128)
//  - bin the point into buf[e]
//  - last-finishing block flips the epoch (all blocks read e before any flip).
__global__ void k_bin(const float* __restrict__ pts, float4* __restrict__ out4) {
    int e = *((volatile int*)&g_epoch);
    int* cnt  = g_cnt2 + e * CELLS;
    int* cntn = g_cnt2 + (1 - e) * CELLS;

    int p = blockIdx.x * blockDim.x + threadIdx.x;
    if (p < CELLS) cntn[p] = 0;                     // restore all-zero invariant

    float x = __ldg(&pts[p * 3 + 0]);
    float y = __ldg(&pts[p * 3 + 1]);
    float z = __ldg(&pts[p * 3 + 2]);

    float4 z4 = make_float4(0.f, 0.f, 0.f, 0.f);
#pragma unroll
    for (int k = 0; k < 6; k++) out4[k * NP + p] = z4;   // zero output region

    int c = cell_of(x, y);
    int pos = atomicAdd(&cnt[c], 1);
    if (pos < CAP) g_bin[c * CAP + pos] = make_float4(x, y, z, (float)p);

    __syncthreads();
    if (threadIdx.x == 0) {
        __threadfence();
        unsigned old = atomicAdd(&g_done, 1u);
        if ((old % 256u) == 255u) {                 // 256 blocks per launch
            g_epoch = 1 - e;
            __threadfence();
        }
    }
}

// One block per anchor. 7 blocks/SM => 1036 concurrent, SINGLE WAVE.
// Stale count buffer is all-zero => count = bufA + bufB, two PARALLEL loads,
// no epoch read, no serial dependency added to the prologue.
__global__ void __launch_bounds__(TPB, 7) k_anchor(
    const float* __restrict__ anch,
    float* __restrict__ out,
    float* __restrict__ counts_out)
{
    int a = blockIdx.x;
    int tid = threadIdx.x;
    int lane = tid & 31;

    // Anchor row = 6 floats at byte offset a*24 (8-aligned): 3 broadcast LDG.64.
    const float2* arow = (const float2*)(anch + a * 6);
    float2 f01 = __ldg(&arow[0]);   // cx, cy
    float2 f23 = __ldg(&arow[1]);   // cz, w
    float2 f45 = __ldg(&arow[2]);   // l, h
    float cx = f01.x, cy = f01.y;
    float w = f23.y, l = f45.x, h = f45.y;
    float hw = w * 0.5f, hl = l * 0.5f;
    float x0 = cx - hw, x1 = cx + hw;
    float y0 = cy - hl, y1 = cy + hl;

    int gx0 = max(0, (int)floorf(x0));
    int gx1 = min(GRID - 1, (int)floorf(x1));
    int gy0 = max(0, (int)floorf(y0));
    int gy1 = min(GRID - 1, (int)floorf(y1));
    int ncx = gx1 - gx0 + 1;
    int ncy = gy1 - gy0 + 1;
    int ncells = ncx * ncy;   // <= 36 (w,l <= 5, cell = 1.0)

    __shared__ int           s_base[40];      // g_bin base per covered cell
    __shared__ int           s_ccnt[40];
    __shared__ int           s_off[40];       // exclusive offset per cell
    __shared__ int           s_total;
    __shared__ unsigned char s_cid[36 * CAP]; // candidate -> covered-cell id
    __shared__ float         s_key[NMAX];     // point index as float (exact)
    __shared__ float         s_px[NMAX], s_py[NMAX], s_pz[NMAX];
    __shared__ int           s_count;

    if (tid == 0) s_count = 0;
    if (tid < ncells) {
        int cgx = gx0 + (tid % ncx);
        int cgy = gy0 + (tid / ncx);
        int c = cgy * GRID + cgx;
        s_base[tid] = c * CAP;
        // live + zero = live; both loads issue in parallel (independent).
        int ca = __ldg(&g_cnt2[c]);
        int cb = __ldg(&g_cnt2[CELLS + c]);
        s_ccnt[tid] = min(ca + cb, CAP);
    }
    __syncthreads();                                   // (1)

    if (tid < ncells) {
        int off = 0;
        for (int j = 0; j < tid; j++) off += s_ccnt[j];
        s_off[tid] = off;
        int cc = s_ccnt[tid];
        for (int k = 0; k < cc; k++) s_cid[off + k] = (unsigned char)tid;
        if (tid == ncells - 1) s_total = off + cc;
    }
    __syncthreads();                                   // (2)

    int total = s_total;

    // Phase A: test candidates (usually one pass: total ~230 < 256), warp-
    // aggregated compaction of key AND coords into shared (order-free).
    for (int i0 = 0; i0 < total; i0 += TPB) {
        int i = i0 + tid;
        bool hit = false;
        float4 r = make_float4(0.f, 0.f, 0.f, 0.f);
        if (i < total) {
            int j = (int)s_cid[i];
            r = __ldg(&g_bin[s_base[j] + (i - s_off[j])]);
            hit = (r.x >= x0 && r.x <= x1 && r.y >= y0 && r.y <= y1 &&
                   r.z >= 0.0f && r.z <= h);
        }
        unsigned bal = __ballot_sync(0xFFFFFFFFu, hit);
        int nb = __popc(bal);
        int base = 0;
        if (lane == 0 && nb) base = atomicAdd(&s_count, nb);
        base = __shfl_sync(0xFFFFFFFFu, base, 0);
        if (hit) {
            int pos = base + __popc(bal & ((1u << lane) - 1u));
            if (pos < NMAX) {
                s_key[pos] = r.w;
                s_px[pos] = r.x; s_py[pos] = r.y; s_pz[pos] = r.z;
            }
        }
    }
    __syncthreads();                                   // (3)

    int cnt = s_count;
    int m = min(cnt, NMAX);
    float* outa = out + (size_t)a * NMAX * 3;

    // Rank-by-counting (broadcast LDS) + direct ranked store. Tail [3m,1536)
    // was zeroed by k_bin; only the 3m live floats are written here.
    for (int s = tid; s < m; s += TPB) {
        float key = s_key[s];
        int r = 0;
        int j = 0;
        for (; j + 4 <= m; j += 4) {
            r += (s_key[j + 0] < key);
            r += (s_key[j + 1] < key);
            r += (s_key[j + 2] < key);
            r += (s_key[j + 3] < key);
        }
        for (; j < m; j++) r += (s_key[j] < key);
        outa[r * 3 + 0] = s_px[s] - cx;
        outa[r * 3 + 1] = s_py[s] - cy;
        outa[r * 3 + 2] = s_pz[s];
    }
    if (tid == 0) counts_out[a] = (float)cnt;
}

extern "C" void kernel_launch(void* const* d_in, const int* in_sizes, int n_in,
                              void* d_out, int out_size) {
    const float* pts  = (const float*)d_in[0];   // (65536, 3) f32
    const float* anch = (const float*)d_in[1];   // (1024, 6)  f32
    float* out = (float*)d_out;                  // 1024*512*3 f32, then 1024 counts
    float* counts_out = out + (size_t)NA * NMAX * 3;

    k_bin<<<NP / 256, 256>>>(pts, (float4*)out);
    k_anchor<<<NA, TPB>>>(anch, out, counts_out);
}